// round 12
// baseline (speedup 1.0000x reference)
#include <cuda_runtime.h>
#include <cuda_bf16.h>

#define HIDDEN 4096
#define TOKENS 16384
#define TP 4
#define EPS 1e-6f

#define THREADS 512
#define V8_PER_ROW (HIDDEN / 8)              // 512 x 32B chunks per row
#define NWARPS (THREADS / 32)                // 16

struct f8 { float v[8]; };

// 256-bit global load (Blackwell): ld.global.v8.b32
__device__ __forceinline__ f8 ldg256(const float* p) {
    f8 r;
    asm volatile("ld.global.v8.b32 {%0,%1,%2,%3,%4,%5,%6,%7}, [%8];"
        : "=f"(r.v[0]), "=f"(r.v[1]), "=f"(r.v[2]), "=f"(r.v[3]),
          "=f"(r.v[4]), "=f"(r.v[5]), "=f"(r.v[6]), "=f"(r.v[7])
        : "l"(p));
    return r;
}

// 256-bit global store (Blackwell): st.global.v8.b32
__device__ __forceinline__ void stg256(float* p, const f8& r) {
    asm volatile("st.global.v8.b32 [%0], {%1,%2,%3,%4,%5,%6,%7,%8};"
        :: "l"(p),
           "f"(r.v[0]), "f"(r.v[1]), "f"(r.v[2]), "f"(r.v[3]),
           "f"(r.v[4]), "f"(r.v[5]), "f"(r.v[6]), "f"(r.v[7])
        : "memory");
}

__global__ __launch_bounds__(THREADS)
void allreduce_rmsnorm_kernel(const float* __restrict__ hs,
                              const float* __restrict__ w,
                              float* __restrict__ out) {
    const int token = blockIdx.x;
    // Each thread owns exactly one 32-byte chunk of the 16KB row.
    const size_t elem = (size_t)token * HIDDEN + (size_t)threadIdx.x * 8;
    const size_t tp_stride = (size_t)TOKENS * HIDDEN;

    // 4 independent 256-bit loads (one per tp rank) -> tp-reduce in regs.
    f8 r0 = ldg256(hs + elem);
    f8 r1 = ldg256(hs + tp_stride + elem);
    f8 r2 = ldg256(hs + 2 * tp_stride + elem);
    f8 r3 = ldg256(hs + 3 * tp_stride + elem);

    f8 acc;
    float ss = 0.0f;
    #pragma unroll
    for (int i = 0; i < 8; i++) {
        const float a = (r0.v[i] + r1.v[i]) + (r2.v[i] + r3.v[i]);
        acc.v[i] = a;
        ss += a * a;
    }

    // Warp-level reduction of sum-of-squares.
    #pragma unroll
    for (int off = 16; off > 0; off >>= 1)
        ss += __shfl_xor_sync(0xFFFFFFFFu, ss, off);

    // Single-barrier block reduction; every warp reduces all 16 partials.
    // Lanes 16..31 mirror lanes 0..15 so the {8,4,2,1} butterfly yields the
    // full block sum in every lane.
    __shared__ float warp_ss[NWARPS];
    const int lane = threadIdx.x & 31;
    const int wid  = threadIdx.x >> 5;
    if (lane == 0) warp_ss[wid] = ss;
    __syncthreads();

    float s = warp_ss[lane & (NWARPS - 1)];
    #pragma unroll
    for (int off = NWARPS / 2; off > 0; off >>= 1)
        s += __shfl_xor_sync(0xFFFFFFFFu, s, off);
    const float inv_rms = rsqrtf(s * (1.0f / (float)HIDDEN) + EPS);

    // Weight chunk for this thread (L2-resident, 16KB total).
    const float4 g0 = __ldg((const float4*)(w + threadIdx.x * 8));
    const float4 g1 = __ldg((const float4*)(w + threadIdx.x * 8) + 1);
    const float gv[8] = { g0.x, g0.y, g0.z, g0.w, g1.x, g1.y, g1.z, g1.w };

    f8 o;
    #pragma unroll
    for (int i = 0; i < 8; i++)
        o.v[i] = acc.v[i] * inv_rms * gv[i];

    stg256(out + elem, o);
}

extern "C" void kernel_launch(void* const* d_in, const int* in_sizes, int n_in,
                              void* d_out, int out_size) {
    const float* hs = (const float*)d_in[0];  // [tp, tokens, hidden] fp32
    // d_in[1] = residual -- unused by the reference computation
    const float* w  = (const float*)d_in[2];  // [hidden] fp32
    float* out = (float*)d_out;               // [tokens, hidden] fp32

    allreduce_rmsnorm_kernel<<<TOKENS, THREADS>>>(hs, w, out);
}